// round 7
// baseline (speedup 1.0000x reference)
#include <cuda_runtime.h>

#define BB 16
#define HH 512
#define WW 512
#define HW (HH*WW)
#define NN (BB*HW)
#define WPR 16                 // words per row
#define WPI (HH*WPR)           // words per image = 8192
#define TOT (BB*WPI)           // total words = 131072

// bit j of word (b,y,w) = pixel x = w*32 + j ; pixel index = 32*wordIdx + j

__device__ unsigned g_F[TOT];
__device__ unsigned g_G[TOT];
// double-buffered union-find state: CCL1 & CCL3 use buffer 0, hole-CCL uses buffer 1
__device__ int g_L0[NN];
__device__ int g_S0[NN];
__device__ int g_L1[NN];
__device__ int g_S1[NN];
__device__ int g_nc[BB];

// ---------------- bit helpers ----------------
__device__ __forceinline__ int runlen(unsigned m, int j) {
    unsigned nt = ~(m >> j);
    return nt ? (__ffs(nt) - 1) : (32 - j);
}
__device__ __forceinline__ unsigned runmask(int j, int e) {
    return (e >= 32) ? 0xffffffffu : (((1u << e) - 1u) << j);
}
// start bit of the in-word run of m containing set bit j
__device__ __forceinline__ int rstart(unsigned m, int j) {
    unsigned zeros = (~m) & (j ? ((1u << j) - 1u) : 0u);
    return zeros ? (32 - __clz(zeros)) : 0;
}
// init labels+sizes at run starts of mask m in word t
__device__ __forceinline__ void init_runs(unsigned m, int t, int* L, int* S) {
    int base = t * 32;
    while (m) {
        int j = __ffs(m) - 1;
        int e = runlen(m, j);
        L[base + j] = base + j;
        S[base + j] = 0;
        m &= ~runmask(j, e);
    }
}

// ---------------- union-find ----------------
// Root chase with atomicCAS path-halving. Safe vs concurrent atomicMin:
// CAS fails if the slot changed; all writers only decrease toward ancestors.
__device__ __forceinline__ int findroot_h(int* L, int i) {
    volatile int* V = L;
    int p;
    while ((p = V[i]) != i) {
        int gp = V[p];
        if (gp == p) return p;
        atomicCAS(&L[i], p, gp);
        i = gp;
    }
    return i;
}

__device__ void unite(int* L, int a, int b) {
    while (true) {
        a = findroot_h(L, a);
        b = findroot_h(L, b);
        if (a == b) return;
        if (a > b) { int t = a; a = b; b = t; }
        int old = atomicMin(&L[b], a);
        if (old == b) return;
        b = old;
    }
}

// resolve root at a run start (immediate when count-compression held)
__device__ __forceinline__ int root_at(const int* L, int i) {
    int r = L[i];
    while (L[r] != r) r = L[r];
    return r;
}

// ---------------- pack + init CCL1 ----------------
__global__ void k_pack(const float* __restrict__ in) {
    int i = blockIdx.x * blockDim.x + threadIdx.x;
    if (i >= NN) return;
    unsigned b = __ballot_sync(0xffffffffu, in[i] > 0.0f);
    if ((i & 31) == 0) {
        int t = i >> 5;
        g_F[t] = b;
        if (t < BB) g_nc[t] = 0;
        init_runs(b, t, g_L0, g_S0);
    }
}

// ---------------- CCL kernels (INV: label the zero bits) ----------------
template<bool INV>
__global__ void k_merge(const unsigned* __restrict__ F, int* L) {
    int t = blockIdx.x * blockDim.x + threadIdx.x;
    if (t >= TOT) return;
    int w = t & 15, y = (t >> 4) & 511;
    unsigned cur = F[t]; if (INV) cur = ~cur;
    if (!cur) return;
    int base = t * 32;
    if (w > 0 && (cur & 1u)) {
        unsigned left = F[t - 1]; if (INV) left = ~left;
        if (left >> 31) unite(L, base, (t - 1) * 32 + rstart(left, 31));
    }
    if (y > 0) {
        unsigned up = F[t - WPR]; if (INV) up = ~up;
        unsigned ov = cur & up;
        unsigned starts = ov & ~(ov << 1);
        while (starts) {
            int j = __ffs(starts) - 1;
            starts &= starts - 1;
            unite(L, base + rstart(cur, j), base - WW + rstart(up, j));
        }
    }
}

// count sizes; owner-only compression write of the final root
template<bool INV, bool NC>
__global__ void k_count(const unsigned* __restrict__ F, int* L, int* S) {
    int t = blockIdx.x * blockDim.x + threadIdx.x;
    if (t >= TOT) return;
    unsigned m = F[t]; if (INV) m = ~m;
    if (!m) return;
    int base = t * 32, b = t >> 13;
    while (m) {
        int j = __ffs(m) - 1;
        int e = runlen(m, j);
        int i = base + j;
        int r = findroot_h(L, i);
        L[i] = r;
        atomicAdd(&S[r], e);
        if (NC && r == i) atomicAdd(&g_nc[b], 1);
        m &= ~runmask(j, e);
    }
}

// filter CCL1 (guarded) + init hole-CCL labels on the INVERTED result (buf 1)
__global__ void k_filter_init(unsigned* F, int min_size) {
    int t = blockIdx.x * blockDim.x + threadIdx.x;
    if (t >= TOT) return;
    unsigned m = F[t];
    unsigned keep = m;
    if (m && g_nc[t >> 13] > 1) {
        int base = t * 32;
        unsigned mm = m;
        while (mm) {
            int j = __ffs(mm) - 1;
            int e = runlen(mm, j);
            if (g_S0[root_at(g_L0, base + j)] < min_size) keep &= ~runmask(j, e);
            mm &= ~runmask(j, e);
        }
        if (keep != m) F[t] = keep;
    }
    init_runs(~keep, t, g_L1, g_S1);   // different buffer -> no race with readers of L0/S0
}

// plain filter (final CCL, buf 0)
__global__ void k_filter(unsigned* F, int min_size) {
    int t = blockIdx.x * blockDim.x + threadIdx.x;
    if (t >= TOT) return;
    unsigned m = F[t];
    if (!m) return;
    if (g_nc[t >> 13] <= 1) return;
    int base = t * 32;
    unsigned keep = m, mm = m;
    while (mm) {
        int j = __ffs(mm) - 1;
        int e = runlen(mm, j);
        if (g_S0[root_at(g_L0, base + j)] < min_size) keep &= ~runmask(j, e);
        mm &= ~runmask(j, e);
    }
    if (keep != m) F[t] = keep;
}

// fill small background components (hole-CCL, buf 1)
__global__ void k_fill(unsigned* F, int thresh) {
    int t = blockIdx.x * blockDim.x + threadIdx.x;
    if (t >= TOT) return;
    unsigned m = ~F[t];
    if (!m) return;
    int base = t * 32;
    unsigned add = 0, mm = m;
    while (mm) {
        int j = __ffs(mm) - 1;
        int e = runlen(mm, j);
        if (g_S1[root_at(g_L1, base + j)] < thresh) add |= runmask(j, e);
        mm &= ~runmask(j, e);
    }
    if (add) F[t] |= add;
}

// ---------------- morphology on bitpacked ----------------
__host__ __device__ constexpr int hwidth(int R, int dy) {
    int w = 0;
    while ((w + 1) * (w + 1) + dy * dy <= R * R) ++w;
    return w;
}

template<int R, bool ER, bool INIT>
__global__ void k_morph(const unsigned* __restrict__ in, unsigned* __restrict__ out) {
    int t = blockIdx.x * blockDim.x + threadIdx.x;
    if (t >= TOT) return;
    int w = t & 15, y = (t >> 4) & 511, b = t >> 13;
    const unsigned* img = in + b * WPI;
    const unsigned border = ER ? 0xffffffffu : 0u;
    unsigned acc = border;
#pragma unroll
    for (int dy = -R; dy <= R; dy++) {
        int yy = y + dy;
        unsigned c, l, r;
        if (yy < 0 || yy >= HH) { c = border; l = border; r = border; }
        else {
            c = img[yy * WPR + w];
            l = (w > 0)  ? img[yy * WPR + w - 1] : border;
            r = (w < 15) ? img[yy * WPR + w + 1] : border;
        }
        unsigned rowacc = c;
        const int wd = hwidth(R, dy);
#pragma unroll
        for (int s = 1; s <= wd; s++) {
            unsigned rs = __funnelshift_r(c, r, s);   // sample x+s
            unsigned ls = __funnelshift_l(l, c, s);   // sample x-s
            if (ER) rowacc &= rs & ls; else rowacc |= rs | ls;
        }
        if (ER) acc &= rowacc; else acc |= rowacc;
    }
    out[t] = acc;
    if (INIT) {                       // prep CCL3 (buf 0; its readers finished long ago)
        if (t < BB) g_nc[t] = 0;
        init_runs(acc, t, g_L0, g_S0);
    }
}

// ---------------- final dilate(disk1) + unpack float ----------------
__global__ void k_out(const unsigned* __restrict__ in, float* __restrict__ out) {
    int g = blockIdx.x * blockDim.x + threadIdx.x;
    if (g >= NN) return;
    int lane = g & 31;
    int t = g >> 5;
    int w = t & 15, y = (t >> 4) & 511, b = t >> 13;
    const unsigned* img = in + b * WPI;
    unsigned c = img[y * WPR + w];
    unsigned l = (w > 0)   ? img[y * WPR + w - 1] : 0u;
    unsigned r = (w < 15)  ? img[y * WPR + w + 1] : 0u;
    unsigned u = (y > 0)   ? img[(y - 1) * WPR + w] : 0u;
    unsigned d = (y < 511) ? img[(y + 1) * WPR + w] : 0u;
    unsigned res = c | u | d | __funnelshift_r(c, r, 1) | __funnelshift_l(l, c, 1);
    out[b * HW + y * WW + w * 32 + lane] = (float)((res >> lane) & 1u);
}

// ---------------- launch ----------------
extern "C" void kernel_launch(void* const* d_in, const int* in_sizes, int n_in,
                              void* d_out, int out_size) {
    (void)in_sizes; (void)n_in; (void)out_size;
    const float* in = (const float*)d_in[0];
    float* out = (float*)d_out;

    unsigned *F, *G;
    int *L0, *S0, *L1, *S1;
    cudaGetSymbolAddress((void**)&F,  g_F);
    cudaGetSymbolAddress((void**)&G,  g_G);
    cudaGetSymbolAddress((void**)&L0, g_L0);
    cudaGetSymbolAddress((void**)&S0, g_S0);
    cudaGetSymbolAddress((void**)&L1, g_L1);
    cudaGetSymbolAddress((void**)&S1, g_S1);

    const int WTPB = 128;
    const int gw = (TOT + WTPB - 1) / WTPB;      // word-granular kernels
    const int PTPB = 256;
    const int gp = (NN + PTPB - 1) / PTPB;       // pixel-granular kernels

    // pack (fg = input > 0) + init CCL1
    k_pack<<<gp, PTPB>>>(in);

    // --- remove_small_objects(fg, 2000, guarded) ---
    k_merge<false><<<gw, WTPB>>>(F, L0);
    k_count<false, true><<<gw, WTPB>>>(F, L0, S0);
    k_filter_init<<<gw, WTPB>>>(F, 2000);        // also inits hole-CCL (buf 1)

    // --- fill small holes: bg components < 301 px ---
    k_merge<true><<<gw, WTPB>>>(F, L1);
    k_count<true, false><<<gw, WTPB>>>(F, L1, S1);
    k_fill<<<gw, WTPB>>>(F, 301);

    // --- erode disk(2), then opening disk(5) ---
    k_morph<2, true , false><<<gw, WTPB>>>(F, G);
    k_morph<5, true , false><<<gw, WTPB>>>(G, F);
    k_morph<5, false, true ><<<gw, WTPB>>>(F, G); // + init CCL3 (buf 0)

    // --- remove_small_objects(fg, 2000, guarded) on G ---
    k_merge<false><<<gw, WTPB>>>(G, L0);
    k_count<false, true><<<gw, WTPB>>>(G, L0, S0);
    k_filter<<<gw, WTPB>>>(G, 2000);

    // --- dilate disk(1) -> float out ---
    k_out<<<gp, PTPB>>>(G, out);
}